// round 4
// baseline (speedup 1.0000x reference)
#include <cuda_runtime.h>
#include <math.h>

#define D_PTS   2562
#define D_PAD   2624          // padded row count for W (41*64)
#define F_BINS  513
#define P_PAIRS 36
#define KDEG    32
#define PK      (P_PAIRS*KDEG)   // 1152
#define BT_N    1000
#define BT_PAD  1024
#define YP      D_PAD             // Y row stride == padded column count
#define TAU_M   4.67

// ---------------- packed f32x2 helpers ----------------------------------------
__device__ __forceinline__ void fma2(unsigned long long& d,
                                     unsigned long long a, unsigned long long b) {
    asm("fma.rn.f32x2 %0, %1, %2, %0;" : "+l"(d) : "l"(a), "l"(b));
}
__device__ __forceinline__ float plo(unsigned long long v) {
    return __uint_as_float((unsigned)v);
}
__device__ __forceinline__ float phi(unsigned long long v) {
    return __uint_as_float((unsigned)(v >> 32));
}

// ---------------- scratch (static __device__ — no allocations) ----------------
__device__ float g_Ac[F_BINS*KDEG];
__device__ float g_As[F_BINS*KDEG];
__device__ float g_M[(size_t)BT_PAD*PK];     // moments   [bt][p*32+k]
__device__ float g_W[(size_t)D_PAD*PK];      // Cheb vals [d][p*32+k]
__device__ float g_Y[(size_t)BT_PAD*YP];     // scores    [bt][d]

__device__ const int c_i0[P_PAIRS] = {0,0,0,0,0,0,0,0, 1,1,1,1,1,1,1, 2,2,2,2,2,2,
                                      3,3,3,3,3, 4,4,4,4, 5,5,5, 6,6, 7};
__device__ const int c_i1[P_PAIRS] = {0,1,2,3,4,5,6,7, 1,2,3,4,5,6,7, 2,3,4,5,6,7,
                                      3,4,5,6,7, 4,5,6,7, 5,6,7, 6,7, 7};

// ---------------- Stage A1: Chebyshev coefficients of cos/sin(omega_f * tau) ----
__global__ void k_coeff() {
    __shared__ double vc[64], vs[64];
    const double PI = 3.141592653589793238462643;
    int f = blockIdx.x;
    int n = threadIdx.x;
    double c = (2.0 * PI * (double)f / 1024.0) * (double)TAU_M;
    double theta = PI * (n + 0.5) / 64.0;
    double x = cos(theta);
    double sn, cn;
    sincos(c * x, &sn, &cn);
    vc[n] = cn; vs[n] = sn;
    __syncthreads();
    int k = threadIdx.x;
    if (k < KDEG) {
        double delta = (PI / 64.0) * (double)k;
        double c0 = cos(0.5 * delta);
        double c1 = cos(1.5 * delta);
        double mult = 2.0 * cos(delta);
        double sc = vc[0]*c0 + vc[1]*c1;
        double ss = vs[0]*c0 + vs[1]*c1;
        double cp = c0, cc = c1;
        for (int nn = 2; nn < 64; nn++) {
            double cnx = mult*cc - cp;
            sc += vc[nn]*cnx; ss += vs[nn]*cnx;
            cp = cc; cc = cnx;
        }
        double scale = (k == 0 ? 1.0 : 2.0) / 64.0;
        g_Ac[f*KDEG + k] = (float)(sc * scale);
        g_As[f*KDEG + k] = (float)(ss * scale);
    }
}

// ---------------- Stage A2: T_k(u_{d,p}) table --------------------------------
__global__ void k_w2(const float* __restrict__ taus, int D) {
    int idx = blockIdx.x * blockDim.x + threadIdx.x;
    if (idx >= D * P_PAIRS) return;
    int d = idx / P_PAIRS, p = idx - d * P_PAIRS;
    float u = (taus[d*8 + c_i0[p]] - taus[d*8 + c_i1[p]]) * (float)(1.0 / TAU_M);
    float* w = g_W + (size_t)d * PK + p * KDEG;
    float tp = 1.0f, tc = u;
    w[0] = 1.0f; w[1] = u;
    float u2 = 2.0f * u;
#pragma unroll
    for (int kk = 2; kk < KDEG; kk++) {
        float tn = fmaf(u2, tc, -tp);
        w[kk] = tn; tp = tc; tc = tn;
    }
}

// ---------------- Stage B: PHAT normalize + moments (packed f32x2) -------------
// packed acc lo = sum xr*ac, hi = sum xi*as; final = lo+hi.
__global__ void __launch_bounds__(288) k_moment(const float* __restrict__ X) {
    __shared__ __align__(16) float  raw[8*72];
    __shared__ __align__(16) float2 Xc[8][36];   // (re,im) normalized
    __shared__ __align__(16) float2 AC[8][32];   // (ac,as)

    int bt  = blockIdx.x;
    int tid = threadIdx.x;
    int k   = tid & 31;
    int pg  = tid >> 5;   // 0..8
    unsigned long long p0 = 0, p1 = 0, p2 = 0, p3 = 0;
    const float* Xb = X + (size_t)bt * (F_BINS * 72);

    for (int f0 = 0; f0 < F_BINS; f0 += 8) {
        int nf = F_BINS - f0; if (nf > 8) nf = 8;
        __syncthreads();
        int tot = nf * 72;
        for (int t = tid; t < tot; t += 288) raw[t] = Xb[f0*72 + t];
        if (tid < nf * 32) {
            ((float2*)AC)[tid] = make_float2(g_Ac[f0*32 + tid], g_As[f0*32 + tid]);
        }
        __syncthreads();
        if (tid < nf * 36) {
            int ff = tid / 36, p = tid - ff * 36;
            float re = raw[ff*72 + p];
            float im = raw[ff*72 + 36 + p];
            float s  = fmaf(re, re, im * im);
            float inv = rsqrtf(fmaxf(s, 1e-36f));
            Xc[ff][p] = make_float2(re * inv, im * inv);
        }
        __syncthreads();
#pragma unroll 8
        for (int ff = 0; ff < nf; ff++) {
            unsigned long long acas = *(const unsigned long long*)&AC[ff][k];
            ulonglong2 xa = *(const ulonglong2*)&Xc[ff][pg*4];
            ulonglong2 xb = *(const ulonglong2*)&Xc[ff][pg*4 + 2];
            fma2(p0, xa.x, acas);
            fma2(p1, xa.y, acas);
            fma2(p2, xb.x, acas);
            fma2(p3, xb.y, acas);
        }
    }
    float* Mo = g_M + (size_t)bt * PK + k;
    Mo[(pg*4 + 0)*32] = plo(p0) + phi(p0);
    Mo[(pg*4 + 1)*32] = plo(p1) + phi(p1);
    Mo[(pg*4 + 2)*32] = plo(p2) + phi(p2);
    Mo[(pg*4 + 3)*32] = plo(p3) + phi(p3);
}

// ---------------- Stage C: Ys = M (1000x1152) * W^T (1152x2562), FFMA2 ---------
// 64x64 tile, 256 threads, 4x4 microtile as 4x(2 packed d-pairs).
// M tile stored DUPLICATED in shared so the broadcast operand is a packed pair.
#define KC 16
__global__ void __launch_bounds__(256) k_gemm() {
    __shared__ __align__(16) float Ms[KC][136];  // duplicated: [kk][2*m], 2*64=128 +8 pad
    __shared__ __align__(16) float Ws[KC][68];
    int d0 = blockIdx.x * 64;
    int m0 = blockIdx.y * 64;
    int tid = threadIdx.x;
    int tx = tid & 15, ty = tid >> 4;
    int lr = tid >> 2;          // 0..63
    int lk = (tid & 3) * 4;     // 0,4,8,12
    const float* Mg = g_M + (size_t)(m0 + lr) * PK + lk;
    const float* Wg = g_W + (size_t)(d0 + lr) * PK + lk;
    unsigned long long acc[4][2] = {};   // [m 0..3][packed d-pair 0..1]

    float4 mv = *(const float4*)(Mg);
    float4 wv = *(const float4*)(Wg);

    for (int k0 = 0; k0 < PK; k0 += KC) {
        *(float2*)&Ms[lk+0][2*lr] = make_float2(mv.x, mv.x);
        *(float2*)&Ms[lk+1][2*lr] = make_float2(mv.y, mv.y);
        *(float2*)&Ms[lk+2][2*lr] = make_float2(mv.z, mv.z);
        *(float2*)&Ms[lk+3][2*lr] = make_float2(mv.w, mv.w);
        Ws[lk+0][lr] = wv.x; Ws[lk+1][lr] = wv.y; Ws[lk+2][lr] = wv.z; Ws[lk+3][lr] = wv.w;
        __syncthreads();
        if (k0 + KC < PK) {          // prefetch next slice while FMAs run
            mv = *(const float4*)(Mg + k0 + KC);
            wv = *(const float4*)(Wg + k0 + KC);
        }
#pragma unroll
        for (int kk = 0; kk < KC; kk++) {
            ulonglong2 bv = *(const ulonglong2*)&Ws[kk][tx*4];
            const unsigned long long* ap = (const unsigned long long*)&Ms[kk][ty*8];
            unsigned long long a0 = ap[0], a1 = ap[1], a2 = ap[2], a3 = ap[3];
            fma2(acc[0][0], a0, bv.x); fma2(acc[0][1], a0, bv.y);
            fma2(acc[1][0], a1, bv.x); fma2(acc[1][1], a1, bv.y);
            fma2(acc[2][0], a2, bv.x); fma2(acc[2][1], a2, bv.y);
            fma2(acc[3][0], a3, bv.x); fma2(acc[3][1], a3, bv.y);
        }
        __syncthreads();
    }
#pragma unroll
    for (int ii = 0; ii < 4; ii++) {
        float4 v = make_float4(plo(acc[ii][0]), phi(acc[ii][0]),
                               plo(acc[ii][1]), phi(acc[ii][1]));
        *(float4*)(g_Y + (size_t)(m0 + ty*4 + ii) * YP + d0 + tx*4) = v;
    }
}

// ---------------- Stage D: argmax over D + gather doas -------------------------
__global__ void __launch_bounds__(256) k_argmax(const float* __restrict__ doas,
                                                float* __restrict__ out, int D) {
    __shared__ float sv[256];
    __shared__ int   si[256];
    int bt = blockIdx.x, tid = threadIdx.x;
    const float* y = g_Y + (size_t)bt * YP;
    float bv = -3.4e38f; int bi = 0;
    for (int d = tid; d < D; d += 256) {
        float v = y[d];
        if (v > bv) { bv = v; bi = d; }
    }
    sv[tid] = bv; si[tid] = bi;
    __syncthreads();
    for (int s = 128; s > 0; s >>= 1) {
        if (tid < s) {
            float v2 = sv[tid + s]; int i2 = si[tid + s];
            if (v2 > sv[tid] || (v2 == sv[tid] && i2 < si[tid])) { sv[tid] = v2; si[tid] = i2; }
        }
        __syncthreads();
    }
    if (tid < 3) out[bt*3 + tid] = doas[si[0]*3 + tid];
}

// ---------------- launch -------------------------------------------------------
extern "C" void kernel_launch(void* const* d_in, const int* in_sizes, int n_in,
                              void* d_out, int out_size) {
    const float* XXs  = (const float*)d_in[0];
    const float* taus = (const float*)d_in[1];
    const float* doas = (const float*)d_in[2];
    float* out = (float*)d_out;

    int D  = in_sizes[1] / 8;            if (D  > D_PTS) D  = D_PTS;
    int BT = in_sizes[0] / (F_BINS*72);  if (BT > BT_N)  BT = BT_N;

    k_coeff<<<F_BINS, 64>>>();
    k_w2<<<(D * P_PAIRS + 255) / 256, 256>>>(taus, D);
    k_moment<<<BT, 288>>>(XXs);
    dim3 g((D + 63) / 64, (BT + 63) / 64);
    k_gemm<<<g, 256>>>();
    k_argmax<<<BT, 256>>>(doas, out, D);
}

// round 6
// speedup vs baseline: 1.3381x; 1.3381x over previous
#include <cuda_runtime.h>
#include <math.h>

#define D_PTS   2562
#define D_PAD   2624          // 41*64
#define F_BINS  513
#define P_PAIRS 36
#define KDEG    32
#define PK      (P_PAIRS*KDEG)   // 1152
#define BT_N    1000
#define BT_PAD  1024
#define YP      D_PAD
#define TAU_M   4.67

// ---------------- packed f32x2 helpers ----------------------------------------
__device__ __forceinline__ void fma2(unsigned long long& d,
                                     unsigned long long a, unsigned long long b) {
    asm("fma.rn.f32x2 %0, %1, %2, %0;" : "+l"(d) : "l"(a), "l"(b));
}
__device__ __forceinline__ float plo(unsigned long long v) {
    return __uint_as_float((unsigned)v);
}
__device__ __forceinline__ float phi(unsigned long long v) {
    return __uint_as_float((unsigned)(v >> 32));
}

// ---------------- scratch ------------------------------------------------------
__device__ float2 g_CS[F_BINS*KDEG];         // (ac,as) packed per (f,k)
__device__ float  g_M[(size_t)BT_PAD*PK];    // moments   [bt][p*32+k]
__device__ float  g_W[(size_t)D_PAD*PK];     // Cheb vals [d][p*32+k]
__device__ float  g_Y[(size_t)BT_PAD*YP];    // scores    [bt][d]

__device__ const int c_i0[P_PAIRS] = {0,0,0,0,0,0,0,0, 1,1,1,1,1,1,1, 2,2,2,2,2,2,
                                      3,3,3,3,3, 4,4,4,4, 5,5,5, 6,6, 7};
__device__ const int c_i1[P_PAIRS] = {0,1,2,3,4,5,6,7, 1,2,3,4,5,6,7, 2,3,4,5,6,7,
                                      3,4,5,6,7, 4,5,6,7, 5,6,7, 6,7, 7};

// ---------------- Stage A1: Chebyshev coefficients (fp64 DCT) ------------------
__global__ void k_coeff() {
    __shared__ double vc[64], vs[64];
    const double PI = 3.141592653589793238462643;
    int f = blockIdx.x;
    int n = threadIdx.x;
    double c = (2.0 * PI * (double)f / 1024.0) * (double)TAU_M;
    double theta = PI * (n + 0.5) / 64.0;
    double x = cos(theta);
    double sn, cn;
    sincos(c * x, &sn, &cn);
    vc[n] = cn; vs[n] = sn;
    __syncthreads();
    int k = threadIdx.x;
    if (k < KDEG) {
        double delta = (PI / 64.0) * (double)k;
        double c0 = cos(0.5 * delta);
        double c1 = cos(1.5 * delta);
        double mult = 2.0 * cos(delta);
        double sc = vc[0]*c0 + vc[1]*c1;
        double ss = vs[0]*c0 + vs[1]*c1;
        double cp = c0, cc = c1;
        for (int nn = 2; nn < 64; nn++) {
            double cnx = mult*cc - cp;
            sc += vc[nn]*cnx; ss += vs[nn]*cnx;
            cp = cc; cc = cnx;
        }
        double scale = (k == 0 ? 1.0 : 2.0) / 64.0;
        g_CS[f*KDEG + k] = make_float2((float)(sc*scale), (float)(ss*scale));
    }
}

// ---------------- Stage A2: T_k(u_{d,p}) table --------------------------------
__global__ void k_w2(const float* __restrict__ taus, int D) {
    int idx = blockIdx.x * blockDim.x + threadIdx.x;
    if (idx >= D * P_PAIRS) return;
    int d = idx / P_PAIRS, p = idx - d * P_PAIRS;
    float u = (taus[d*8 + c_i0[p]] - taus[d*8 + c_i1[p]]) * (float)(1.0 / TAU_M);
    float* w = g_W + (size_t)d * PK + p * KDEG;
    float tp = 1.0f, tc = u;
    w[0] = 1.0f; w[1] = u;
    float u2 = 2.0f * u;
#pragma unroll
    for (int kk = 2; kk < KDEG; kk++) {
        float tn = fmaf(u2, tc, -tp);
        w[kk] = tn; tp = tc; tc = tn;
    }
}

// ---------------- Stage B: PHAT normalize + moments (pipelined, f32x2) ---------
// One sync per 8-freq chunk; raw+coeff prefetched one chunk ahead in registers;
// Xc / AC double-buffered in shared.
__global__ void __launch_bounds__(288) k_moment(const float* __restrict__ X) {
    __shared__ __align__(16) float2 Xc[2][8][36];
    __shared__ __align__(16) float2 ACs[2][256];

    int bt  = blockIdx.x;
    int tid = threadIdx.x;
    int k   = tid & 31;
    int pg  = tid >> 5;           // 0..8
    int ffl = tid / 36;           // 0..7 (288 = 8*36 exactly)
    int pl  = tid - ffl * 36;
    const float* Xb = X + (size_t)bt * (F_BINS * 72);
    unsigned long long p0 = 0, p1 = 0, p2 = 0, p3 = 0;

    // prefetch chunk 0
    float re = Xb[ffl*72 + pl];
    float im = Xb[ffl*72 + 36 + pl];
    float2 cs = make_float2(0.f, 0.f);
    if (tid < 256) cs = g_CS[tid];

    for (int c = 0; c < 64; c++) {     // 64 full chunks of 8 freqs
        int buf = c & 1;
        float s   = fmaf(re, re, im * im);
        float inv = rsqrtf(fmaxf(s, 1e-36f));
        Xc[buf][ffl][pl] = make_float2(re * inv, im * inv);
        if (tid < 256) ACs[buf][tid] = cs;
        __syncthreads();
        // prefetch chunk c+1 (c=63 prefetches the 1-freq tail)
        {
            int f0n = (c + 1) * 8;
            int nfn = F_BINS - f0n; if (nfn > 8) nfn = 8;
            if (ffl < nfn) {
                re = Xb[(f0n + ffl)*72 + pl];
                im = Xb[(f0n + ffl)*72 + 36 + pl];
            }
            if (tid < nfn * 32) cs = g_CS[f0n*32 + tid];
        }
#pragma unroll
        for (int ff = 0; ff < 8; ff++) {
            unsigned long long acas = *(const unsigned long long*)&ACs[buf][ff*32 + k];
            ulonglong2 xa = *(const ulonglong2*)&Xc[buf][ff][pg*4];
            ulonglong2 xb = *(const ulonglong2*)&Xc[buf][ff][pg*4 + 2];
            fma2(p0, xa.x, acas);
            fma2(p1, xa.y, acas);
            fma2(p2, xb.x, acas);
            fma2(p3, xb.y, acas);
        }
    }
    // tail chunk: f = 512 only (buf 0; chunk 63 used buf 1)
    {
        if (ffl < 1) {
            float s   = fmaf(re, re, im * im);
            float inv = rsqrtf(fmaxf(s, 1e-36f));
            Xc[0][0][pl] = make_float2(re * inv, im * inv);
        }
        if (tid < 32) ACs[0][tid] = cs;
        __syncthreads();
        unsigned long long acas = *(const unsigned long long*)&ACs[0][k];
        ulonglong2 xa = *(const ulonglong2*)&Xc[0][0][pg*4];
        ulonglong2 xb = *(const ulonglong2*)&Xc[0][0][pg*4 + 2];
        fma2(p0, xa.x, acas);
        fma2(p1, xa.y, acas);
        fma2(p2, xb.x, acas);
        fma2(p3, xb.y, acas);
    }
    float* Mo = g_M + (size_t)bt * PK + k;
    Mo[(pg*4 + 0)*32] = plo(p0) + phi(p0);
    Mo[(pg*4 + 1)*32] = plo(p1) + phi(p1);
    Mo[(pg*4 + 2)*32] = plo(p2) + phi(p2);
    Mo[(pg*4 + 3)*32] = plo(p3) + phi(p3);
}

// ---------------- Stage C: Ys = M (1000x1152) * W^T, plain FFMA ---------------
// 128(m) x 64(d) tile, 256 threads, 8x4 microtile, KC=32, coalesced loaders.
#define KC 32
#define BM 128
#define BD 64
__global__ void __launch_bounds__(256) k_gemm() {
    __shared__ __align__(16) float Ms[KC][BM+4];  // [k][m], stride 132
    __shared__ __align__(16) float Ws[KC][BD+4];  // [k][d], stride 68
    int d0 = blockIdx.x * BD;
    int m0 = blockIdx.y * BM;
    int tid = threadIdx.x;
    int tx = tid & 15, ty = tid >> 4;     // consumer: d=tx*4, m=ty*8
    int lk = (tid & 7) * 4;               // loader k offset 0..28
    int lr = tid >> 3;                    // loader row 0..31
    const float* Mg = g_M + (size_t)(m0 + lr) * PK + lk;
    const float* Wg = g_W + (size_t)(d0 + lr) * PK + lk;
    float acc[8][4] = {};

    float4 mpre[4], wpre[2];
#pragma unroll
    for (int i = 0; i < 4; i++) mpre[i] = *(const float4*)(Mg + (size_t)32*i*PK);
#pragma unroll
    for (int i = 0; i < 2; i++) wpre[i] = *(const float4*)(Wg + (size_t)32*i*PK);

    for (int k0 = 0; k0 < PK; k0 += KC) {
#pragma unroll
        for (int i = 0; i < 4; i++) {
            Ms[lk+0][lr+32*i] = mpre[i].x;
            Ms[lk+1][lr+32*i] = mpre[i].y;
            Ms[lk+2][lr+32*i] = mpre[i].z;
            Ms[lk+3][lr+32*i] = mpre[i].w;
        }
#pragma unroll
        for (int i = 0; i < 2; i++) {
            Ws[lk+0][lr+32*i] = wpre[i].x;
            Ws[lk+1][lr+32*i] = wpre[i].y;
            Ws[lk+2][lr+32*i] = wpre[i].z;
            Ws[lk+3][lr+32*i] = wpre[i].w;
        }
        __syncthreads();
        if (k0 + KC < PK) {
#pragma unroll
            for (int i = 0; i < 4; i++) mpre[i] = *(const float4*)(Mg + k0 + KC + (size_t)32*i*PK);
#pragma unroll
            for (int i = 0; i < 2; i++) wpre[i] = *(const float4*)(Wg + k0 + KC + (size_t)32*i*PK);
        }
#pragma unroll
        for (int kk = 0; kk < KC; kk++) {
            float4 b  = *(const float4*)&Ws[kk][tx*4];
            float4 a0 = *(const float4*)&Ms[kk][ty*8];
            float4 a1 = *(const float4*)&Ms[kk][ty*8 + 4];
            acc[0][0] = fmaf(a0.x, b.x, acc[0][0]);
            acc[0][1] = fmaf(a0.x, b.y, acc[0][1]);
            acc[0][2] = fmaf(a0.x, b.z, acc[0][2]);
            acc[0][3] = fmaf(a0.x, b.w, acc[0][3]);
            acc[1][0] = fmaf(a0.y, b.x, acc[1][0]);
            acc[1][1] = fmaf(a0.y, b.y, acc[1][1]);
            acc[1][2] = fmaf(a0.y, b.z, acc[1][2]);
            acc[1][3] = fmaf(a0.y, b.w, acc[1][3]);
            acc[2][0] = fmaf(a0.z, b.x, acc[2][0]);
            acc[2][1] = fmaf(a0.z, b.y, acc[2][1]);
            acc[2][2] = fmaf(a0.z, b.z, acc[2][2]);
            acc[2][3] = fmaf(a0.z, b.w, acc[2][3]);
            acc[3][0] = fmaf(a0.w, b.x, acc[3][0]);
            acc[3][1] = fmaf(a0.w, b.y, acc[3][1]);
            acc[3][2] = fmaf(a0.w, b.z, acc[3][2]);
            acc[3][3] = fmaf(a0.w, b.w, acc[3][3]);
            acc[4][0] = fmaf(a1.x, b.x, acc[4][0]);
            acc[4][1] = fmaf(a1.x, b.y, acc[4][1]);
            acc[4][2] = fmaf(a1.x, b.z, acc[4][2]);
            acc[4][3] = fmaf(a1.x, b.w, acc[4][3]);
            acc[5][0] = fmaf(a1.y, b.x, acc[5][0]);
            acc[5][1] = fmaf(a1.y, b.y, acc[5][1]);
            acc[5][2] = fmaf(a1.y, b.z, acc[5][2]);
            acc[5][3] = fmaf(a1.y, b.w, acc[5][3]);
            acc[6][0] = fmaf(a1.z, b.x, acc[6][0]);
            acc[6][1] = fmaf(a1.z, b.y, acc[6][1]);
            acc[6][2] = fmaf(a1.z, b.z, acc[6][2]);
            acc[6][3] = fmaf(a1.z, b.w, acc[6][3]);
            acc[7][0] = fmaf(a1.w, b.x, acc[7][0]);
            acc[7][1] = fmaf(a1.w, b.y, acc[7][1]);
            acc[7][2] = fmaf(a1.w, b.z, acc[7][2]);
            acc[7][3] = fmaf(a1.w, b.w, acc[7][3]);
        }
        __syncthreads();
    }
#pragma unroll
    for (int ii = 0; ii < 8; ii++) {
        float4 v = make_float4(acc[ii][0], acc[ii][1], acc[ii][2], acc[ii][3]);
        *(float4*)(g_Y + (size_t)(m0 + ty*8 + ii) * YP + d0 + tx*4) = v;
    }
}

// ---------------- Stage D: argmax over D + gather doas -------------------------
__global__ void __launch_bounds__(256) k_argmax(const float* __restrict__ doas,
                                                float* __restrict__ out, int D) {
    __shared__ float sv[256];
    __shared__ int   si[256];
    int bt = blockIdx.x, tid = threadIdx.x;
    const float* y = g_Y + (size_t)bt * YP;
    float bv = -3.4e38f; int bi = 0;
    for (int d = tid; d < D; d += 256) {
        float v = y[d];
        if (v > bv) { bv = v; bi = d; }
    }
    sv[tid] = bv; si[tid] = bi;
    __syncthreads();
    for (int s = 128; s > 0; s >>= 1) {
        if (tid < s) {
            float v2 = sv[tid + s]; int i2 = si[tid + s];
            if (v2 > sv[tid] || (v2 == sv[tid] && i2 < si[tid])) { sv[tid] = v2; si[tid] = i2; }
        }
        __syncthreads();
    }
    if (tid < 3) out[bt*3 + tid] = doas[si[0]*3 + tid];
}

// ---------------- launch -------------------------------------------------------
extern "C" void kernel_launch(void* const* d_in, const int* in_sizes, int n_in,
                              void* d_out, int out_size) {
    const float* XXs  = (const float*)d_in[0];
    const float* taus = (const float*)d_in[1];
    const float* doas = (const float*)d_in[2];
    float* out = (float*)d_out;

    int D  = in_sizes[1] / 8;            if (D  > D_PTS) D  = D_PTS;
    int BT = in_sizes[0] / (F_BINS*72);  if (BT > BT_N)  BT = BT_N;

    k_coeff<<<F_BINS, 64>>>();
    k_w2<<<(D * P_PAIRS + 255) / 256, 256>>>(taus, D);
    k_moment<<<BT, 288>>>(XXs);
    dim3 g(D_PAD / BD, (BT + BM - 1) / BM);
    k_gemm<<<g, 256>>>();
    k_argmax<<<BT, 256>>>(doas, out, D);
}

// round 8
// speedup vs baseline: 1.3854x; 1.0353x over previous
#include <cuda_runtime.h>
#include <math.h>

#define D_PTS   2562
#define D_PAD   2624          // 41*64
#define F_BINS  513
#define P_PAIRS 36
#define KDEG    32
#define PK      (P_PAIRS*KDEG)   // 1152
#define BT_N    1000
#define BT_PAD  1024
#define YP      D_PAD
#define TAU_M   4.67

// ---------------- packed f32x2 helpers ----------------------------------------
__device__ __forceinline__ void fma2(unsigned long long& d,
                                     unsigned long long a, unsigned long long b) {
    asm("fma.rn.f32x2 %0, %1, %2, %0;" : "+l"(d) : "l"(a), "l"(b));
}
__device__ __forceinline__ float plo(unsigned long long v) {
    return __uint_as_float((unsigned)v);
}
__device__ __forceinline__ float phi(unsigned long long v) {
    return __uint_as_float((unsigned)(v >> 32));
}
#define PACKDUP(out, v) asm("mov.b64 %0, {%1, %1};" : "=l"(out) : "f"(v))

// ---------------- scratch ------------------------------------------------------
__device__ float2 g_CS[F_BINS*KDEG];         // (ac,as) packed per (f,k)
__device__ float  g_M[(size_t)BT_PAD*PK];    // moments   [bt][p*32+k]
__device__ float  g_W[(size_t)D_PAD*PK];     // Cheb vals [d][p*32+k]
__device__ float  g_Y[(size_t)BT_PAD*YP];    // scores    [bt][d]

__device__ const int c_i0[P_PAIRS] = {0,0,0,0,0,0,0,0, 1,1,1,1,1,1,1, 2,2,2,2,2,2,
                                      3,3,3,3,3, 4,4,4,4, 5,5,5, 6,6, 7};
__device__ const int c_i1[P_PAIRS] = {0,1,2,3,4,5,6,7, 1,2,3,4,5,6,7, 2,3,4,5,6,7,
                                      3,4,5,6,7, 4,5,6,7, 5,6,7, 6,7, 7};

// ---------------- Stage A1: Chebyshev coefficients (fp64 DCT) ------------------
__global__ void k_coeff() {
    __shared__ double vc[64], vs[64];
    const double PI = 3.141592653589793238462643;
    int f = blockIdx.x;
    int n = threadIdx.x;
    double c = (2.0 * PI * (double)f / 1024.0) * (double)TAU_M;
    double theta = PI * (n + 0.5) / 64.0;
    double x = cos(theta);
    double sn, cn;
    sincos(c * x, &sn, &cn);
    vc[n] = cn; vs[n] = sn;
    __syncthreads();
    int k = threadIdx.x;
    if (k < KDEG) {
        double delta = (PI / 64.0) * (double)k;
        double c0 = cos(0.5 * delta);
        double c1 = cos(1.5 * delta);
        double mult = 2.0 * cos(delta);
        double sc = vc[0]*c0 + vc[1]*c1;
        double ss = vs[0]*c0 + vs[1]*c1;
        double cp = c0, cc = c1;
        for (int nn = 2; nn < 64; nn++) {
            double cnx = mult*cc - cp;
            sc += vc[nn]*cnx; ss += vs[nn]*cnx;
            cp = cc; cc = cnx;
        }
        double scale = (k == 0 ? 1.0 : 2.0) / 64.0;
        g_CS[f*KDEG + k] = make_float2((float)(sc*scale), (float)(ss*scale));
    }
}

// ---------------- Stage A2: T_k(u_{d,p}) table --------------------------------
__global__ void k_w2(const float* __restrict__ taus, int D) {
    int idx = blockIdx.x * blockDim.x + threadIdx.x;
    if (idx >= D * P_PAIRS) return;
    int d = idx / P_PAIRS, p = idx - d * P_PAIRS;
    float u = (taus[d*8 + c_i0[p]] - taus[d*8 + c_i1[p]]) * (float)(1.0 / TAU_M);
    float* w = g_W + (size_t)d * PK + p * KDEG;
    float tp = 1.0f, tc = u;
    w[0] = 1.0f; w[1] = u;
    float u2 = 2.0f * u;
#pragma unroll
    for (int kk = 2; kk < KDEG; kk++) {
        float tn = fmaf(u2, tc, -tp);
        w[kk] = tn; tp = tc; tc = tn;
    }
}

// ---------------- Stage B: PHAT normalize + moments (pipelined, f32x2) ---------
__global__ void __launch_bounds__(288) k_moment(const float* __restrict__ X) {
    __shared__ __align__(16) float2 Xc[2][8][36];
    __shared__ __align__(16) float2 ACs[2][256];

    int bt  = blockIdx.x;
    int tid = threadIdx.x;
    int k   = tid & 31;
    int pg  = tid >> 5;           // 0..8
    int ffl = tid / 36;           // 0..7 (288 = 8*36 exactly)
    int pl  = tid - ffl * 36;
    const float* Xb = X + (size_t)bt * (F_BINS * 72);
    unsigned long long p0 = 0, p1 = 0, p2 = 0, p3 = 0;

    // prefetch chunk 0
    float re = Xb[ffl*72 + pl];
    float im = Xb[ffl*72 + 36 + pl];
    float2 cs = make_float2(0.f, 0.f);
    if (tid < 256) cs = g_CS[tid];

    for (int c = 0; c < 64; c++) {     // 64 full chunks of 8 freqs
        int buf = c & 1;
        float s   = fmaf(re, re, im * im);
        float inv = rsqrtf(fmaxf(s, 1e-36f));
        Xc[buf][ffl][pl] = make_float2(re * inv, im * inv);
        if (tid < 256) ACs[buf][tid] = cs;
        __syncthreads();
        // prefetch chunk c+1 (c=63 prefetches the 1-freq tail)
        {
            int f0n = (c + 1) * 8;
            int nfn = F_BINS - f0n; if (nfn > 8) nfn = 8;
            if (ffl < nfn) {
                re = Xb[(f0n + ffl)*72 + pl];
                im = Xb[(f0n + ffl)*72 + 36 + pl];
            }
            if (tid < nfn * 32) cs = g_CS[f0n*32 + tid];
        }
#pragma unroll
        for (int ff = 0; ff < 8; ff++) {
            unsigned long long acas = *(const unsigned long long*)&ACs[buf][ff*32 + k];
            ulonglong2 xa = *(const ulonglong2*)&Xc[buf][ff][pg*4];
            ulonglong2 xb = *(const ulonglong2*)&Xc[buf][ff][pg*4 + 2];
            fma2(p0, xa.x, acas);
            fma2(p1, xa.y, acas);
            fma2(p2, xb.x, acas);
            fma2(p3, xb.y, acas);
        }
    }
    // tail chunk: f = 512 only (buf 0; chunk 63 used buf 1)
    {
        if (ffl < 1) {
            float s   = fmaf(re, re, im * im);
            float inv = rsqrtf(fmaxf(s, 1e-36f));
            Xc[0][0][pl] = make_float2(re * inv, im * inv);
        }
        if (tid < 32) ACs[0][tid] = cs;
        __syncthreads();
        unsigned long long acas = *(const unsigned long long*)&ACs[0][k];
        ulonglong2 xa = *(const ulonglong2*)&Xc[0][0][pg*4];
        ulonglong2 xb = *(const ulonglong2*)&Xc[0][0][pg*4 + 2];
        fma2(p0, xa.x, acas);
        fma2(p1, xa.y, acas);
        fma2(p2, xb.x, acas);
        fma2(p3, xb.y, acas);
    }
    float* Mo = g_M + (size_t)bt * PK + k;
    Mo[(pg*4 + 0)*32] = plo(p0) + phi(p0);
    Mo[(pg*4 + 1)*32] = plo(p1) + phi(p1);
    Mo[(pg*4 + 2)*32] = plo(p2) + phi(p2);
    Mo[(pg*4 + 3)*32] = plo(p3) + phi(p3);
}

// ---------------- Stage C: Ys = M * W^T, packed FFMA2 (m-paired) ---------------
// 128(m) x 64(d) tile, 256 threads. Microtile per thread: 8m x 4d as
// 4 packed m-pairs x 4 d. a-pairs load natively from scalar Ms rows (broadcast);
// b duplicates built via mov.b64 (ALU pipe). Conflict-free LDS on both operands.
#define KC 32
#define BM 128
#define BD 64
__global__ void __launch_bounds__(256) k_gemm() {
    __shared__ __align__(16) float Ms[KC][BM+4];  // [k][m], stride 132 (528B, 16B-mult)
    __shared__ __align__(16) float Ws[KC][BD+4];  // [k][d], stride 68
    int d0 = blockIdx.x * BD;
    int m0 = blockIdx.y * BM;
    int tid = threadIdx.x;
    int tx = tid & 15, ty = tid >> 4;     // consumer: d=tx*4, m=ty*8
    int lk = (tid & 7) * 4;               // loader k offset 0..28
    int lr = tid >> 3;                    // loader row 0..31
    const float* Mg = g_M + (size_t)(m0 + lr) * PK + lk;
    const float* Wg = g_W + (size_t)(d0 + lr) * PK + lk;
    unsigned long long acc[4][4] = {};    // [m-pair][d]

    float4 mpre[4], wpre[2];
#pragma unroll
    for (int i = 0; i < 4; i++) mpre[i] = *(const float4*)(Mg + (size_t)32*i*PK);
#pragma unroll
    for (int i = 0; i < 2; i++) wpre[i] = *(const float4*)(Wg + (size_t)32*i*PK);

    for (int k0 = 0; k0 < PK; k0 += KC) {
#pragma unroll
        for (int i = 0; i < 4; i++) {
            Ms[lk+0][lr+32*i] = mpre[i].x;
            Ms[lk+1][lr+32*i] = mpre[i].y;
            Ms[lk+2][lr+32*i] = mpre[i].z;
            Ms[lk+3][lr+32*i] = mpre[i].w;
        }
#pragma unroll
        for (int i = 0; i < 2; i++) {
            Ws[lk+0][lr+32*i] = wpre[i].x;
            Ws[lk+1][lr+32*i] = wpre[i].y;
            Ws[lk+2][lr+32*i] = wpre[i].z;
            Ws[lk+3][lr+32*i] = wpre[i].w;
        }
        __syncthreads();
        if (k0 + KC < PK) {
#pragma unroll
            for (int i = 0; i < 4; i++) mpre[i] = *(const float4*)(Mg + k0 + KC + (size_t)32*i*PK);
#pragma unroll
            for (int i = 0; i < 2; i++) wpre[i] = *(const float4*)(Wg + k0 + KC + (size_t)32*i*PK);
        }
#pragma unroll
        for (int kk = 0; kk < KC; kk++) {
            float4 bq = *(const float4*)&Ws[kk][tx*4];
            ulonglong2 a01 = *(const ulonglong2*)&Ms[kk][ty*8];
            ulonglong2 a23 = *(const ulonglong2*)&Ms[kk][ty*8 + 4];
            unsigned long long pb0, pb1, pb2, pb3;
            PACKDUP(pb0, bq.x);
            PACKDUP(pb1, bq.y);
            PACKDUP(pb2, bq.z);
            PACKDUP(pb3, bq.w);
            fma2(acc[0][0], a01.x, pb0); fma2(acc[0][1], a01.x, pb1);
            fma2(acc[0][2], a01.x, pb2); fma2(acc[0][3], a01.x, pb3);
            fma2(acc[1][0], a01.y, pb0); fma2(acc[1][1], a01.y, pb1);
            fma2(acc[1][2], a01.y, pb2); fma2(acc[1][3], a01.y, pb3);
            fma2(acc[2][0], a23.x, pb0); fma2(acc[2][1], a23.x, pb1);
            fma2(acc[2][2], a23.x, pb2); fma2(acc[2][3], a23.x, pb3);
            fma2(acc[3][0], a23.y, pb0); fma2(acc[3][1], a23.y, pb1);
            fma2(acc[3][2], a23.y, pb2); fma2(acc[3][3], a23.y, pb3);
        }
        __syncthreads();
    }
#pragma unroll
    for (int mp = 0; mp < 4; mp++) {
        float4 vlo = make_float4(plo(acc[mp][0]), plo(acc[mp][1]),
                                 plo(acc[mp][2]), plo(acc[mp][3]));
        float4 vhi = make_float4(phi(acc[mp][0]), phi(acc[mp][1]),
                                 phi(acc[mp][2]), phi(acc[mp][3]));
        *(float4*)(g_Y + (size_t)(m0 + ty*8 + 2*mp + 0) * YP + d0 + tx*4) = vlo;
        *(float4*)(g_Y + (size_t)(m0 + ty*8 + 2*mp + 1) * YP + d0 + tx*4) = vhi;
    }
}

// ---------------- Stage D: argmax over D + gather doas -------------------------
__global__ void __launch_bounds__(256) k_argmax(const float* __restrict__ doas,
                                                float* __restrict__ out, int D) {
    __shared__ float sv[256];
    __shared__ int   si[256];
    int bt = blockIdx.x, tid = threadIdx.x;
    const float* y = g_Y + (size_t)bt * YP;
    float bv = -3.4e38f; int bi = 0;
    for (int d = tid; d < D; d += 256) {
        float v = y[d];
        if (v > bv) { bv = v; bi = d; }
    }
    sv[tid] = bv; si[tid] = bi;
    __syncthreads();
    for (int s = 128; s > 0; s >>= 1) {
        if (tid < s) {
            float v2 = sv[tid + s]; int i2 = si[tid + s];
            if (v2 > sv[tid] || (v2 == sv[tid] && i2 < si[tid])) { sv[tid] = v2; si[tid] = i2; }
        }
        __syncthreads();
    }
    if (tid < 3) out[bt*3 + tid] = doas[si[0]*3 + tid];
}

// ---------------- launch -------------------------------------------------------
extern "C" void kernel_launch(void* const* d_in, const int* in_sizes, int n_in,
                              void* d_out, int out_size) {
    const float* XXs  = (const float*)d_in[0];
    const float* taus = (const float*)d_in[1];
    const float* doas = (const float*)d_in[2];
    float* out = (float*)d_out;

    int D  = in_sizes[1] / 8;            if (D  > D_PTS) D  = D_PTS;
    int BT = in_sizes[0] / (F_BINS*72);  if (BT > BT_N)  BT = BT_N;

    k_coeff<<<F_BINS, 64>>>();
    k_w2<<<(D * P_PAIRS + 255) / 256, 256>>>(taus, D);
    k_moment<<<BT, 288>>>(XXs);
    dim3 g(D_PAD / BD, (BT + BM - 1) / BM);
    k_gemm<<<g, 256>>>();
    k_argmax<<<BT, 256>>>(doas, out, D);
}